// round 13
// baseline (speedup 1.0000x reference)
#include <cuda_runtime.h>
#include <cuda_bf16.h>

// Problem constants
#define CC    768        // channels
#define NO    197        // tokens per frame (N_origin)
#define FRn   8          // FRAMES
#define BBn   8          // batch after frame-fold (64/8)
#define NNt   1576       // FRn*NO
#define HHn   12         // heads
#define HDn   64         // head dim
#define MMn   204        // gathered tokens (8 cls + 196)
#define ROWSn 12608      // BBn*NNt (= 64*197)
#define GRn   1632       // BBn*MMn
#define NBH   96         // BBn*HHn

// HMMA GEMM smem layout (bf16 elements)
#define KPAD    40                       // padded K per smem row (80B stride)
#define TILE_E  (128 * KPAD)             // 5120 elems per tile
#define OFF_AHI 0
#define OFF_ALO TILE_E
#define OFF_WHI (2 * TILE_E)
#define OFF_WLO (3 * TILE_E)
#define STAGE_E (4 * TILE_E)             // 20480 elems per stage
#define SMEM_GEMM (2 * STAGE_E * 2)      // 81920 bytes (double buffered)

// Attention smem layout (bf16 element offsets), 64-query tile, 128 threads.
// Q+K phase region: [0, 39168). V (after phase A) aliases [0, 27648).
#define QKP  72                          // Q/K smem row stride (144 B)
#define VPP  216                         // Vt row stride (m, padded 204->216)
#define SQHI 0                           // Q hi: 64 x 72
#define SQLO 4608
#define SKHI 9216                        // K hi: 208 x 72
#define SKLO 24192                       // K lo: ends at 39168
#define SV2HI 0                          // V hi: 64 x 216 (aliases Q+K)
#define SV2LO 13824                      // V lo: ends at 27648
#define SMEM_ATT_E 39168
#define SMEM_ATT   (SMEM_ATT_E * 2)      // 78336 B -> 2 CTAs/SM

typedef unsigned long long ull;
typedef __nv_bfloat16 bf16;

// ---------------------------------------------------------------------------
// Scratch (device globals; no allocation allowed)
// ---------------------------------------------------------------------------
__device__ __align__(16) bf16 g_xhi[ROWSn * CC];
__device__ __align__(16) bf16 g_xlo[ROWSn * CC];
__device__ __align__(16) bf16 g_wqhi[3 * CC * CC];
__device__ __align__(16) bf16 g_wqlo[3 * CC * CC];
__device__ __align__(16) bf16 g_wphi[CC * CC];
__device__ __align__(16) bf16 g_wplo[CC * CC];
__device__ __align__(16) bf16 g_qhi[ROWSn * CC];      // Q projection split
__device__ __align__(16) bf16 g_qlo[ROWSn * CC];
__device__ __align__(16) bf16 g_khi[NBH * MMn * HDn]; // K [bh][m][d]
__device__ __align__(16) bf16 g_klo[NBH * MMn * HDn];
__device__ __align__(16) bf16 g_vthi[NBH * HDn * VPP]; // V^T [bh][d][m], padded
__device__ __align__(16) bf16 g_vtlo[NBH * HDn * VPP];
__device__ __align__(16) bf16 g_ohi[ROWSn * CC];      // attention out split
__device__ __align__(16) bf16 g_olo[ROWSn * CC];

// token index of gathered column m (matches _build_indices_mask)
__device__ __forceinline__ int token_of(int m) {
    if (m < 8) return m * NO;            // cls tokens
    int r = m - 8;
    int f, j;
    if (r < 100) { f = r / 25; j = r - f * 25; }     // frames 0..3, len 25
    else { r -= 100; f = 4 + r / 24; j = r % 24; }   // frames 4..7, len 24
    return f * NO + 1 + f + 8 * j;
}

// fp32 pair -> (bf16 hi pair, bf16 lo pair)
__device__ __forceinline__ void split2f(float x, float y,
                                        __nv_bfloat162& h, __nv_bfloat162& l) {
    bf16 h0 = __float2bfloat16(x), h1 = __float2bfloat16(y);
    h = __nv_bfloat162(h0, h1);
    l = __floats2bfloat162_rn(x - __bfloat162float(h0), y - __bfloat162float(h1));
}
// fp32 pair -> packed u32 (hi, lo)
__device__ __forceinline__ void split_pack(float x, float y,
                                           unsigned& h, unsigned& l) {
    __nv_bfloat162 hh, ll;
    split2f(x, y, hh, ll);
    h = *(unsigned*)&hh; l = *(unsigned*)&ll;
}

// ---------------------------------------------------------------------------
// fp32 -> (bf16 hi, bf16 lo) split conversion, 4 elems/thread
// ---------------------------------------------------------------------------
__global__ __launch_bounds__(256) void cvt_hilo(
    const float* __restrict__ s, bf16* __restrict__ h, bf16* __restrict__ l, int n4)
{
    int i = blockIdx.x * 256 + threadIdx.x;
    if (i >= n4) return;
    float4 v = ((const float4*)s)[i];
    __nv_bfloat162 h0, l0, h1, l1;
    split2f(v.x, v.y, h0, l0);
    split2f(v.z, v.w, h1, l1);
    __nv_bfloat162* hp = (__nv_bfloat162*)h;
    __nv_bfloat162* lp = (__nv_bfloat162*)l;
    hp[2 * i] = h0; hp[2 * i + 1] = h1;
    lp[2 * i] = l0; lp[2 * i + 1] = l1;
}

// zero the pad columns (204..215) of g_vt so HMMA never sees NaN garbage
__global__ __launch_bounds__(256) void vt_zero_pad()
{
    int bh = blockIdx.x;
    for (int i = threadIdx.x; i < HDn * 12; i += 256) {
        int d = i / 12, pc = 204 + i % 12;
        size_t g = ((size_t)bh * HDn + d) * VPP + pc;
        g_vthi[g] = __float2bfloat16(0.f);
        g_vtlo[g] = __float2bfloat16(0.f);
    }
}

// ---------------------------------------------------------------------------
// HMMA primitives
// ---------------------------------------------------------------------------
__device__ __forceinline__ unsigned smem_u32(const void* p) {
    return (unsigned)__cvta_generic_to_shared(p);
}
__device__ __forceinline__ void ldsm4(unsigned addr, unsigned& r0, unsigned& r1,
                                      unsigned& r2, unsigned& r3) {
    asm volatile("ldmatrix.sync.aligned.m8n8.x4.shared.b16 {%0,%1,%2,%3}, [%4];"
                 : "=r"(r0), "=r"(r1), "=r"(r2), "=r"(r3) : "r"(addr));
}
__device__ __forceinline__ void mma16816(float* d, const unsigned* a, const unsigned* b) {
    asm volatile(
        "mma.sync.aligned.m16n8k16.row.col.f32.bf16.bf16.f32 "
        "{%0,%1,%2,%3}, {%4,%5,%6,%7}, {%8,%9}, {%0,%1,%2,%3};"
        : "+f"(d[0]), "+f"(d[1]), "+f"(d[2]), "+f"(d[3])
        : "r"(a[0]), "r"(a[1]), "r"(a[2]), "r"(a[3]), "r"(b[0]), "r"(b[1]));
}

// global->smem slab load: A (hi,lo) rows pA0/pA1 (nullptr => zero), W cols cW0/cW1
__device__ __forceinline__ void load_slab(
    bf16* s, const bf16* pA0h, const bf16* pA0l, const bf16* pA1h, const bf16* pA1l,
    const bf16* pW0h, const bf16* pW0l, const bf16* pW1h, const bf16* pW1l,
    int k0, int t)
{
    const int row = t >> 2;
    const int sub = (t & 3) * 8;       // bf16 elems
    const int so0 = row * KPAD + sub;
    const int so1 = (row + 64) * KPAD + sub;
    const uint4 z = make_uint4(0, 0, 0, 0);
    uint4 ah0 = pA0h ? *(const uint4*)(pA0h + k0 + sub) : z;
    uint4 ah1 = pA1h ? *(const uint4*)(pA1h + k0 + sub) : z;
    uint4 al0 = pA0l ? *(const uint4*)(pA0l + k0 + sub) : z;
    uint4 al1 = pA1l ? *(const uint4*)(pA1l + k0 + sub) : z;
    uint4 wh0 = *(const uint4*)(pW0h + k0 + sub);
    uint4 wh1 = *(const uint4*)(pW1h + k0 + sub);
    uint4 wl0 = *(const uint4*)(pW0l + k0 + sub);
    uint4 wl1 = *(const uint4*)(pW1l + k0 + sub);
    *(uint4*)(s + OFF_AHI + so0) = ah0;  *(uint4*)(s + OFF_AHI + so1) = ah1;
    *(uint4*)(s + OFF_ALO + so0) = al0;  *(uint4*)(s + OFF_ALO + so1) = al1;
    *(uint4*)(s + OFF_WHI + so0) = wh0;  *(uint4*)(s + OFF_WHI + so1) = wh1;
    *(uint4*)(s + OFF_WLO + so0) = wl0;  *(uint4*)(s + OFF_WLO + so1) = wl1;
}

// compute one 32-wide K slab: warp tile 32x64, 3-way split-bf16 accumulate
__device__ __forceinline__ void hmma_slab(const bf16* s, int wm, int wn, int lane,
                                          float acc[2][8][4])
{
#pragma unroll
    for (int ks = 0; ks < 2; ks++) {
        const int arow = wm * 32 + (lane & 15);
        const int acol = ks * 16 + (lane >> 4) * 8;
        unsigned ahi[2][4], alo[2][4];
#pragma unroll
        for (int mt = 0; mt < 2; mt++) {
            ldsm4(smem_u32(s + OFF_AHI + (arow + mt * 16) * KPAD + acol),
                  ahi[mt][0], ahi[mt][1], ahi[mt][2], ahi[mt][3]);
            ldsm4(smem_u32(s + OFF_ALO + (arow + mt * 16) * KPAD + acol),
                  alo[mt][0], alo[mt][1], alo[mt][2], alo[mt][3]);
        }
        const int brow = wn * 64 + (lane & 7) + ((lane >> 4) << 3);
        const int bcol = ks * 16 + ((lane >> 3) & 1) * 8;
        unsigned bhi[8][2], blo[8][2];
#pragma unroll
        for (int np = 0; np < 4; np++) {
            unsigned r0, r1, r2, r3;
            ldsm4(smem_u32(s + OFF_WHI + (brow + np * 16) * KPAD + bcol), r0, r1, r2, r3);
            bhi[2 * np][0] = r0; bhi[2 * np][1] = r1;
            bhi[2 * np + 1][0] = r2; bhi[2 * np + 1][1] = r3;
            ldsm4(smem_u32(s + OFF_WLO + (brow + np * 16) * KPAD + bcol), r0, r1, r2, r3);
            blo[2 * np][0] = r0; blo[2 * np][1] = r1;
            blo[2 * np + 1][0] = r2; blo[2 * np + 1][1] = r3;
        }
#pragma unroll
        for (int mt = 0; mt < 2; mt++)
#pragma unroll
            for (int nf = 0; nf < 8; nf++) {
                mma16816(acc[mt][nf], ahi[mt], bhi[nf]);
                mma16816(acc[mt][nf], ahi[mt], blo[nf]);
                mma16816(acc[mt][nf], alo[mt], bhi[nf]);
            }
    }
}

// full mainloop: fills acc for this block's 128x128 tile
__device__ __forceinline__ void hmma_mainloop(
    const bf16* pA0h, const bf16* pA0l, const bf16* pA1h, const bf16* pA1l,
    const bf16* pW0h, const bf16* pW0l, const bf16* pW1h, const bf16* pW1l,
    float acc[2][8][4])
{
    extern __shared__ bf16 sbuf[];
    const int t = threadIdx.x;
    const int wid = t >> 5, lane = t & 31;
    const int wm = wid & 3, wn = wid >> 2;

#pragma unroll
    for (int i = 0; i < 2; i++)
#pragma unroll
        for (int j = 0; j < 8; j++)
#pragma unroll
            for (int v = 0; v < 4; v++) acc[i][j][v] = 0.f;

    load_slab(sbuf, pA0h, pA0l, pA1h, pA1l, pW0h, pW0l, pW1h, pW1l, 0, t);
    __syncthreads();
    for (int sl = 0; sl < 24; sl++) {
        if (sl + 1 < 24)
            load_slab(sbuf + ((sl + 1) & 1) * STAGE_E,
                      pA0h, pA0l, pA1h, pA1l, pW0h, pW0l, pW1h, pW1l,
                      (sl + 1) * 32, t);
        hmma_slab(sbuf + (sl & 1) * STAGE_E, wm, wn, lane, acc);
        __syncthreads();
    }
}

// ---------------------------------------------------------------------------
// Merged GEMM 1+2: blocks [0,594) do Q projection, blocks [594,750) do the
// gathered K/V projection. Single launch fills the tail wave.
// ---------------------------------------------------------------------------
__global__ __launch_bounds__(256) void gemm_qkv_hmma()
{
    const int bid = blockIdx.x;
    const int t = threadIdx.x;
    const int wid = t >> 5, lane = t & 31;
    const int wm = wid & 3, wn = wid >> 2;
    const int quad = lane >> 2, qp = lane & 3;

    if (bid < 594) {
        // ---- Q projection: 12608 x 768 ----
        const int row0 = (bid / 6) * 128, col0 = (bid % 6) * 128;
        const int rA0 = row0 + (t >> 2), rA1 = rA0 + 64;
        const int cW0 = col0 + (t >> 2), cW1 = cW0 + 64;
        const bf16* pA0h = (rA0 < ROWSn) ? g_xhi + (size_t)rA0 * CC : nullptr;
        const bf16* pA0l = (rA0 < ROWSn) ? g_xlo + (size_t)rA0 * CC : nullptr;
        const bf16* pA1h = (rA1 < ROWSn) ? g_xhi + (size_t)rA1 * CC : nullptr;
        const bf16* pA1l = (rA1 < ROWSn) ? g_xlo + (size_t)rA1 * CC : nullptr;

        float acc[2][8][4];
        hmma_mainloop(pA0h, pA0l, pA1h, pA1l,
                      g_wqhi + (size_t)cW0 * CC, g_wqlo + (size_t)cW0 * CC,
                      g_wqhi + (size_t)cW1 * CC, g_wqlo + (size_t)cW1 * CC, acc);

#pragma unroll
        for (int mt = 0; mt < 2; mt++)
#pragma unroll
            for (int nf = 0; nf < 8; nf++) {
                int r = row0 + wm * 32 + mt * 16 + quad;
                int c = col0 + wn * 64 + nf * 8 + qp * 2;
                __nv_bfloat162 h, l;
                if (r < ROWSn) {
                    split2f(acc[mt][nf][0], acc[mt][nf][1], h, l);
                    *(__nv_bfloat162*)&g_qhi[(size_t)r * CC + c] = h;
                    *(__nv_bfloat162*)&g_qlo[(size_t)r * CC + c] = l;
                }
                if (r + 8 < ROWSn) {
                    split2f(acc[mt][nf][2], acc[mt][nf][3], h, l);
                    *(__nv_bfloat162*)&g_qhi[(size_t)(r + 8) * CC + c] = h;
                    *(__nv_bfloat162*)&g_qlo[(size_t)(r + 8) * CC + c] = l;
                }
            }
    } else {
        // ---- gathered K/V projection: 1632 x 1536 ----
        const int idx = bid - 594;
        const int row0 = (idx / 12) * 128, col0 = (idx % 12) * 128;

        const bf16* pA[2][2] = {{nullptr, nullptr}, {nullptr, nullptr}};
#pragma unroll
        for (int i = 0; i < 2; i++) {
            int gr = row0 + (t >> 2) + i * 64;
            if (gr < GRn) {
                int b = gr / MMn, m = gr - b * MMn;
                size_t src = (size_t)(b * NNt + token_of(m)) * CC;
                pA[i][0] = g_xhi + src; pA[i][1] = g_xlo + src;
            }
        }
        const int cW0 = col0 + (t >> 2), cW1 = cW0 + 64;
        const bf16* wbase_h = g_wqhi + (size_t)768 * CC;
        const bf16* wbase_l = g_wqlo + (size_t)768 * CC;

        float acc[2][8][4];
        hmma_mainloop(pA[0][0], pA[0][1], pA[1][0], pA[1][1],
                      wbase_h + (size_t)cW0 * CC, wbase_l + (size_t)cW0 * CC,
                      wbase_h + (size_t)cW1 * CC, wbase_l + (size_t)cW1 * CC, acc);

#pragma unroll
        for (int mt = 0; mt < 2; mt++)
#pragma unroll
            for (int nf = 0; nf < 8; nf++) {
#pragma unroll
                for (int up = 0; up < 2; up++) {
                    int gr = row0 + wm * 32 + mt * 16 + quad + up * 8;
                    if (gr >= GRn) continue;
                    int b = gr / MMn, m = gr - b * MMn;
                    int c = col0 + wn * 64 + nf * 8 + qp * 2;
                    float vx = acc[mt][nf][2 * up], vy = acc[mt][nf][2 * up + 1];
                    if (c < 768) {
                        int h = c >> 6, d = c & 63;
                        int bh = b * HHn + h;
                        __nv_bfloat162 hh, ll;
                        split2f(vx, vy, hh, ll);
                        size_t g = ((size_t)bh * MMn + m) * HDn + d;
                        *(__nv_bfloat162*)&g_khi[g] = hh;
                        *(__nv_bfloat162*)&g_klo[g] = ll;
                    } else {
                        int c2 = c - 768;
                        int h = c2 >> 6, d = c2 & 63;
                        int bh = b * HHn + h;
                        bf16 h0 = __float2bfloat16(vx);
                        bf16 h1 = __float2bfloat16(vy);
                        bf16 l0 = __float2bfloat16(vx - __bfloat162float(h0));
                        bf16 l1 = __float2bfloat16(vy - __bfloat162float(h1));
                        size_t g0 = ((size_t)bh * HDn + d) * VPP + m;
                        size_t g1 = ((size_t)bh * HDn + d + 1) * VPP + m;
                        g_vthi[g0] = h0; g_vtlo[g0] = l0;
                        g_vthi[g1] = h1; g_vtlo[g1] = l1;
                    }
                }
            }
    }
}

// ---------------------------------------------------------------------------
// Attention (tensor), 64-query tile, 128 threads, 78.3KB smem -> 2 CTAs/SM.
// Phase A: S = Q K^T (split HMMA, 4 warps x 16 rows, S in regs, K=64)
// Phase B: mask + exp in registers, quad shfl row-sum (NO smem, NO barriers)
// Phase C: O = P V^T with P fragments built in-register from S fragments
//          (m16n8k16 C-layout == A-layout identity); V resident in smem
//          (aliased over dead Q+K region). Normalization in epilogue.
// ---------------------------------------------------------------------------
__global__ __launch_bounds__(128, 2) void attn_hmma()
{
    extern __shared__ bf16 sb[];
    const int bh = blockIdx.x, qt = blockIdx.y;
    const int b = bh / HHn, h = bh % HHn;
    const int n0 = qt * 64;
    const int t = threadIdx.x, wid = t >> 5, lane = t & 31;

    // --- loads: Q 64x64, K 208x64 (hi+lo) ---
    for (int i = t; i < 512; i += 128) {
        int row = i >> 3, u = (i & 7) * 8;
        int qn = n0 + row; if (qn >= NNt) qn = NNt - 1;
        size_t g = (size_t)(b * NNt + qn) * CC + h * HDn + u;
        *(uint4*)(sb + SQHI + row * QKP + u) = *(const uint4*)(g_qhi + g);
        *(uint4*)(sb + SQLO + row * QKP + u) = *(const uint4*)(g_qlo + g);
    }
    const uint4 z4 = make_uint4(0, 0, 0, 0);
    for (int i = t; i < 1664; i += 128) {
        int row = i >> 3, u = (i & 7) * 8;
        uint4 vh = z4, vl = z4;
        if (row < MMn) {
            size_t g = ((size_t)bh * MMn + row) * HDn + u;
            vh = *(const uint4*)(g_khi + g);
            vl = *(const uint4*)(g_klo + g);
        }
        *(uint4*)(sb + SKHI + row * QKP + u) = vh;
        *(uint4*)(sb + SKLO + row * QKP + u) = vl;
    }
    __syncthreads();

    // --- Phase A: S = Q K^T, warp owns 16 rows, all 208 key cols ---
    float sacc[26][4];
#pragma unroll
    for (int i = 0; i < 26; i++)
#pragma unroll
        for (int v = 0; v < 4; v++) sacc[i][v] = 0.f;

    const int m0 = wid * 16;
#pragma unroll
    for (int ks = 0; ks < 4; ks++) {
        unsigned ah[4], al[4];
        const int arow = m0 + (lane & 15);
        const int acol = ks * 16 + (lane >> 4) * 8;
        ldsm4(smem_u32(sb + SQHI + arow * QKP + acol), ah[0], ah[1], ah[2], ah[3]);
        ldsm4(smem_u32(sb + SQLO + arow * QKP + acol), al[0], al[1], al[2], al[3]);
        const int brow_base = (lane & 7) + ((lane >> 4) << 3);
        const int bcol = ks * 16 + ((lane >> 3) & 1) * 8;
#pragma unroll
        for (int np = 0; np < 13; np++) {
            unsigned kh[4], kl[4];
            ldsm4(smem_u32(sb + SKHI + (np * 16 + brow_base) * QKP + bcol),
                  kh[0], kh[1], kh[2], kh[3]);
            ldsm4(smem_u32(sb + SKLO + (np * 16 + brow_base) * QKP + bcol),
                  kl[0], kl[1], kl[2], kl[3]);
            mma16816(sacc[2 * np],     ah, kh);
            mma16816(sacc[2 * np],     ah, kl);
            mma16816(sacc[2 * np],     al, kh);
            mma16816(sacc[2 * np + 1], ah, kh + 2);
            mma16816(sacc[2 * np + 1], ah, kl + 2);
            mma16816(sacc[2 * np + 1], al, kh + 2);
        }
    }
    __syncthreads();   // all Q/K smem reads done before V overwrites the region

    // --- V load into freed region (overlaps phase B's MUFU work) ---
    for (int i = t; i < 1728; i += 128) {
        int row = i / 27, u = (i % 27) * 8;
        size_t g = ((size_t)bh * HDn + row) * VPP + u;
        *(uint4*)(sb + SV2HI + row * VPP + u) = *(const uint4*)(g_vthi + g);
        *(uint4*)(sb + SV2LO + row * VPP + u) = *(const uint4*)(g_vtlo + g);
    }

    // --- Phase B: mask + exp + row sums (registers only) ---
    const int ra = m0 + (lane >> 2);
    int qa = n0 + ra, qb = qa + 8;
    int qac = qa < NNt ? qa : NNt - 1;
    int qbc = qb < NNt ? qb : NNt - 1;
    int fa = qac / NO, fb = qbc / NO;
    int csa = (fa < 4) ? (8 + 25 * fa) : (108 + 24 * (fa - 4));
    int cea = csa + ((fa < 4) ? 25 : 24);
    int csb = (fb < 4) ? (8 + 25 * fb) : (108 + 24 * (fb - 4));
    int ceb = csb + ((fb < 4) ? 25 : 24);

    float suma = 0.f, sumb = 0.f;
#pragma unroll
    for (int nf = 0; nf < 26; nf++) {
        int c0 = nf * 8 + (lane & 3) * 2;
        int c1 = c0 + 1;
        float ma0 = (c0 < 8 || (c0 >= csa && c0 < cea)) ? 0.125f : 0.1f;
        float ma1 = (c1 < 8 || (c1 >= csa && c1 < cea)) ? 0.125f : 0.1f;
        float mb0 = (c0 < 8 || (c0 >= csb && c0 < ceb)) ? 0.125f : 0.1f;
        float mb1 = (c1 < 8 || (c1 >= csb && c1 < ceb)) ? 0.125f : 0.1f;
        float pa0 = (c0 < MMn) ? __expf(sacc[nf][0] * ma0) : 0.f;
        float pa1 = (c1 < MMn) ? __expf(sacc[nf][1] * ma1) : 0.f;
        float pb0 = (c0 < MMn) ? __expf(sacc[nf][2] * mb0) : 0.f;
        float pb1 = (c1 < MMn) ? __expf(sacc[nf][3] * mb1) : 0.f;
        sacc[nf][0] = pa0; sacc[nf][1] = pa1;
        sacc[nf][2] = pb0; sacc[nf][3] = pb1;
        suma += pa0 + pa1; sumb += pb0 + pb1;
    }
    suma += __shfl_xor_sync(0xffffffffu, suma, 1);
    suma += __shfl_xor_sync(0xffffffffu, suma, 2);
    sumb += __shfl_xor_sync(0xffffffffu, sumb, 1);
    sumb += __shfl_xor_sync(0xffffffffu, sumb, 2);
    const float inva = 1.f / suma, invb = 1.f / sumb;

    __syncthreads();   // V resident

    // --- Phase C: O = P V^T, P fragments from registers (C==A layout) ---
    float oacc[8][4];
#pragma unroll
    for (int j = 0; j < 8; j++)
#pragma unroll
        for (int v = 0; v < 4; v++) oacc[j][v] = 0.f;

    const int brow_base = (lane & 7) + ((lane >> 4) << 3);
#pragma unroll 1
    for (int kk = 0; kk < 13; kk++) {
        // A fragments (hi, lo) for this k16 chunk from S fragments 2kk, 2kk+1
        unsigned phf[4], plf[4];
        split_pack(sacc[2 * kk][0],     sacc[2 * kk][1],     phf[0], plf[0]);
        split_pack(sacc[2 * kk][2],     sacc[2 * kk][3],     phf[1], plf[1]);
        split_pack(sacc[2 * kk + 1][0], sacc[2 * kk + 1][1], phf[2], plf[2]);
        split_pack(sacc[2 * kk + 1][2], sacc[2 * kk + 1][3], phf[3], plf[3]);

        const int bcol = kk * 16 + ((lane >> 3) & 1) * 8;
#pragma unroll
        for (int np = 0; np < 4; np++) {
            unsigned r0, r1, r2, r3, s0, s1, s2, s3;
            ldsm4(smem_u32(sb + SV2HI + (brow_base + np * 16) * VPP + bcol),
                  r0, r1, r2, r3);
            ldsm4(smem_u32(sb + SV2LO + (brow_base + np * 16) * VPP + bcol),
                  s0, s1, s2, s3);
            unsigned vh0[2] = {r0, r1}, vh1[2] = {r2, r3};
            unsigned vl0[2] = {s0, s1}, vl1[2] = {s2, s3};
            mma16816(oacc[2 * np],     phf, vh0);
            mma16816(oacc[2 * np],     plf, vh0);
            mma16816(oacc[2 * np],     phf, vl0);
            mma16816(oacc[2 * np + 1], phf, vh1);
            mma16816(oacc[2 * np + 1], plf, vh1);
            mma16816(oacc[2 * np + 1], phf, vl1);
        }
    }

    // --- epilogue: normalize + split O to g_ohi/g_olo ---
    const int quad = lane >> 2, qp = lane & 3;
#pragma unroll
    for (int nf = 0; nf < 8; nf++) {
        int r = n0 + m0 + quad;
        int c = h * HDn + nf * 8 + qp * 2;
        __nv_bfloat162 hh, ll;
        if (r < NNt) {
            size_t g = (size_t)(b * NNt + r) * CC + c;
            split2f(oacc[nf][0] * inva, oacc[nf][1] * inva, hh, ll);
            *(__nv_bfloat162*)&g_ohi[g] = hh;
            *(__nv_bfloat162*)&g_olo[g] = ll;
        }
        if (r + 8 < NNt) {
            size_t g = (size_t)(b * NNt + r + 8) * CC + c;
            split2f(oacc[nf][2] * invb, oacc[nf][3] * invb, hh, ll);
            *(__nv_bfloat162*)&g_ohi[g] = hh;
            *(__nv_bfloat162*)&g_olo[g] = ll;
        }
    }
}

// ---------------------------------------------------------------------------
// GEMM 3: out = O @ proj_w^T + proj_b   (12608 x 768, K=768), grid (99, 6)
// ---------------------------------------------------------------------------
__global__ __launch_bounds__(256) void gemm_proj_hmma(
    const float* __restrict__ bias, float* __restrict__ Cout)
{
    const int t = threadIdx.x;
    const int row0 = blockIdx.x * 128, col0 = blockIdx.y * 128;
    const int wid = t >> 5, lane = t & 31;
    const int wm = wid & 3, wn = wid >> 2;

    const int rA0 = row0 + (t >> 2), rA1 = rA0 + 64;
    const int cW0 = col0 + (t >> 2), cW1 = cW0 + 64;
    const bf16* pA0h = (rA0 < ROWSn) ? g_ohi + (size_t)rA0 * CC : nullptr;
    const bf16* pA0l = (rA0 < ROWSn) ? g_olo + (size_t)rA0 * CC : nullptr;
    const bf16* pA1h = (rA1 < ROWSn) ? g_ohi + (size_t)rA1 * CC : nullptr;
    const bf16* pA1l = (rA1 < ROWSn) ? g_olo + (size_t)rA1 * CC : nullptr;

    float acc[2][8][4];
    hmma_mainloop(pA0h, pA0l, pA1h, pA1l,
                  g_wphi + (size_t)cW0 * CC, g_wplo + (size_t)cW0 * CC,
                  g_wphi + (size_t)cW1 * CC, g_wplo + (size_t)cW1 * CC, acc);

    const int quad = lane >> 2, qp = lane & 3;
#pragma unroll
    for (int nf = 0; nf < 8; nf++) {
        int c = col0 + wn * 64 + nf * 8 + qp * 2;
        float2 bv = *(const float2*)&bias[c];
#pragma unroll
        for (int mt = 0; mt < 2; mt++) {
            int r = row0 + wm * 32 + mt * 16 + quad;
            if (r < ROWSn)
                *(float2*)&Cout[(size_t)r * CC + c] =
                    make_float2(acc[mt][nf][0] + bv.x, acc[mt][nf][1] + bv.y);
            if (r + 8 < ROWSn)
                *(float2*)&Cout[(size_t)(r + 8) * CC + c] =
                    make_float2(acc[mt][nf][2] + bv.x, acc[mt][nf][3] + bv.y);
        }
    }
}

// ---------------------------------------------------------------------------
extern "C" void kernel_launch(void* const* d_in, const int* in_sizes, int n_in,
                              void* d_out, int out_size)
{
    const float* x      = (const float*)d_in[0];
    const float* qkv_w  = (const float*)d_in[1];
    const float* proj_w = (const float*)d_in[2];
    const float* proj_b = (const float*)d_in[3];
    float* out = (float*)d_out;

    cudaFuncSetAttribute(gemm_qkv_hmma,
                         cudaFuncAttributeMaxDynamicSharedMemorySize, SMEM_GEMM);
    cudaFuncSetAttribute(gemm_proj_hmma,
                         cudaFuncAttributeMaxDynamicSharedMemorySize, SMEM_GEMM);
    cudaFuncSetAttribute(attn_hmma,
                         cudaFuncAttributeMaxDynamicSharedMemorySize, SMEM_ATT);

    bf16 *xhi, *xlo, *wqhi, *wqlo, *wphi, *wplo;
    cudaGetSymbolAddress((void**)&xhi, g_xhi);
    cudaGetSymbolAddress((void**)&xlo, g_xlo);
    cudaGetSymbolAddress((void**)&wqhi, g_wqhi);
    cudaGetSymbolAddress((void**)&wqlo, g_wqlo);
    cudaGetSymbolAddress((void**)&wphi, g_wphi);
    cudaGetSymbolAddress((void**)&wplo, g_wplo);

    dim3 blk(256);
    int n4x = ROWSn * CC / 4;
    int n4q = 3 * CC * CC / 4;
    int n4p = CC * CC / 4;
    cvt_hilo<<<(n4x + 255) / 256, blk>>>(x, xhi, xlo, n4x);
    cvt_hilo<<<(n4q + 255) / 256, blk>>>(qkv_w, wqhi, wqlo, n4q);
    cvt_hilo<<<(n4p + 255) / 256, blk>>>(proj_w, wphi, wplo, n4p);
    vt_zero_pad<<<NBH, blk>>>();

    // merged Q + K/V projections (594 + 156 blocks)
    gemm_qkv_hmma<<<750, blk, SMEM_GEMM>>>();
    // attention: 96 bh x 25 query tiles of 64, 128 threads, 2 CTAs/SM
    attn_hmma<<<dim3(NBH, 25), 128, SMEM_ATT>>>();
    // output projection + bias
    gemm_proj_hmma<<<dim3(99, 6), blk, SMEM_GEMM>>>(proj_b, out);
}

// round 14
// speedup vs baseline: 1.2188x; 1.2188x over previous
#include <cuda_runtime.h>
#include <cuda_bf16.h>

// Problem constants
#define CC    768        // channels
#define NO    197        // tokens per frame (N_origin)
#define FRn   8          // FRAMES
#define BBn   8          // batch after frame-fold (64/8)
#define NNt   1576       // FRn*NO
#define HHn   12         // heads
#define HDn   64         // head dim
#define MMn   204        // gathered tokens (8 cls + 196)
#define ROWSn 12608      // BBn*NNt (= 64*197)
#define GRn   1632       // BBn*MMn
#define NBH   96         // BBn*HHn

// HMMA GEMM smem layout (bf16 elements)
#define KPAD    40                       // padded K per smem row (80B stride)
#define TILE_E  (128 * KPAD)             // 5120 elems per tile
#define OFF_AHI 0
#define OFF_ALO TILE_E
#define OFF_WHI (2 * TILE_E)
#define OFF_WLO (3 * TILE_E)
#define STAGE_E (4 * TILE_E)             // 20480 elems per stage
#define SMEM_GEMM (2 * STAGE_E * 2)      // 81920 bytes (double buffered)

// Attention smem layout (bf16 element offsets) - R10 design: 128-query tile
#define QKP  72                          // Q/K smem row stride (144 B)
#define VPP  216                         // Vt / P smem row stride (432 B)
#define SQHI 0                           // Q hi: 128 x 72
#define SQLO 9216
#define SKHI 18432                       // K hi: 208 x 72
#define SKLO 33408
#define SPHI 0                           // P hi: 128 x 216 (aliases Q+K)
#define SPLO 27648
#define SVHI 55296                       // Vt hi: 64 x 216
#define SVLO 69120
#define SMEM_ATT_E 82944
#define SMEM_ATT   (SMEM_ATT_E * 2)      // 165888 B

typedef unsigned long long ull;
typedef __nv_bfloat16 bf16;

// ---------------------------------------------------------------------------
// Scratch (device globals; no allocation allowed)
// ---------------------------------------------------------------------------
__device__ __align__(16) bf16 g_xhi[ROWSn * CC];
__device__ __align__(16) bf16 g_xlo[ROWSn * CC];
__device__ __align__(16) bf16 g_wqhi[3 * CC * CC];
__device__ __align__(16) bf16 g_wqlo[3 * CC * CC];
__device__ __align__(16) bf16 g_wphi[CC * CC];
__device__ __align__(16) bf16 g_wplo[CC * CC];
__device__ __align__(16) bf16 g_qhi[ROWSn * CC];      // Q projection split
__device__ __align__(16) bf16 g_qlo[ROWSn * CC];
__device__ __align__(16) bf16 g_khi[NBH * MMn * HDn]; // K [bh][m][d]
__device__ __align__(16) bf16 g_klo[NBH * MMn * HDn];
__device__ __align__(16) bf16 g_vthi[NBH * HDn * VPP]; // V^T [bh][d][m], padded
__device__ __align__(16) bf16 g_vtlo[NBH * HDn * VPP];
__device__ __align__(16) bf16 g_ohi[ROWSn * CC];      // attention out split
__device__ __align__(16) bf16 g_olo[ROWSn * CC];

// token index of gathered column m (matches _build_indices_mask)
__device__ __forceinline__ int token_of(int m) {
    if (m < 8) return m * NO;            // cls tokens
    int r = m - 8;
    int f, j;
    if (r < 100) { f = r / 25; j = r - f * 25; }     // frames 0..3, len 25
    else { r -= 100; f = 4 + r / 24; j = r % 24; }   // frames 4..7, len 24
    return f * NO + 1 + f + 8 * j;
}

// fp32 pair -> (bf16 hi pair, bf16 lo pair)
__device__ __forceinline__ void split2f(float x, float y,
                                        __nv_bfloat162& h, __nv_bfloat162& l) {
    bf16 h0 = __float2bfloat16(x), h1 = __float2bfloat16(y);
    h = __nv_bfloat162(h0, h1);
    l = __floats2bfloat162_rn(x - __bfloat162float(h0), y - __bfloat162float(h1));
}

// ---------------------------------------------------------------------------
// fp32 -> (bf16 hi, bf16 lo) split conversion, 4 elems/thread
// ---------------------------------------------------------------------------
__global__ __launch_bounds__(256) void cvt_hilo(
    const float* __restrict__ s, bf16* __restrict__ h, bf16* __restrict__ l, int n4)
{
    int i = blockIdx.x * 256 + threadIdx.x;
    if (i >= n4) return;
    float4 v = ((const float4*)s)[i];
    __nv_bfloat162 h0, l0, h1, l1;
    split2f(v.x, v.y, h0, l0);
    split2f(v.z, v.w, h1, l1);
    __nv_bfloat162* hp = (__nv_bfloat162*)h;
    __nv_bfloat162* lp = (__nv_bfloat162*)l;
    hp[2 * i] = h0; hp[2 * i + 1] = h1;
    lp[2 * i] = l0; lp[2 * i + 1] = l1;
}

// zero the pad columns (204..215) of g_vt so HMMA never sees NaN garbage
__global__ __launch_bounds__(256) void vt_zero_pad()
{
    int bh = blockIdx.x;
    for (int i = threadIdx.x; i < HDn * 12; i += 256) {
        int d = i / 12, pc = 204 + i % 12;
        size_t g = ((size_t)bh * HDn + d) * VPP + pc;
        g_vthi[g] = __float2bfloat16(0.f);
        g_vtlo[g] = __float2bfloat16(0.f);
    }
}

// ---------------------------------------------------------------------------
// HMMA primitives
// ---------------------------------------------------------------------------
__device__ __forceinline__ unsigned smem_u32(const void* p) {
    return (unsigned)__cvta_generic_to_shared(p);
}
__device__ __forceinline__ void ldsm4(unsigned addr, unsigned& r0, unsigned& r1,
                                      unsigned& r2, unsigned& r3) {
    asm volatile("ldmatrix.sync.aligned.m8n8.x4.shared.b16 {%0,%1,%2,%3}, [%4];"
                 : "=r"(r0), "=r"(r1), "=r"(r2), "=r"(r3) : "r"(addr));
}
__device__ __forceinline__ void mma16816(float* d, const unsigned* a, const unsigned* b) {
    asm volatile(
        "mma.sync.aligned.m16n8k16.row.col.f32.bf16.bf16.f32 "
        "{%0,%1,%2,%3}, {%4,%5,%6,%7}, {%8,%9}, {%0,%1,%2,%3};"
        : "+f"(d[0]), "+f"(d[1]), "+f"(d[2]), "+f"(d[3])
        : "r"(a[0]), "r"(a[1]), "r"(a[2]), "r"(a[3]), "r"(b[0]), "r"(b[1]));
}

// 16B async copy with zero-fill when pred is false
__device__ __forceinline__ void cpa16(const bf16* dst, const bf16* src, bool pred) {
    unsigned d = smem_u32(dst);
    const void* s = pred ? (const void*)src : (const void*)g_xhi;
    int sz = pred ? 16 : 0;
    asm volatile("cp.async.cg.shared.global [%0], [%1], 16, %2;"
                 :: "r"(d), "l"(s), "r"(sz));
}
#define CP_COMMIT() asm volatile("cp.async.commit_group;")
#define CP_WAIT0()  asm volatile("cp.async.wait_group 0;")

// async slab load: A (hi,lo) rows pA0/pA1 (nullptr => zero-fill), W cols cW0/cW1
__device__ __forceinline__ void load_slab_async(
    bf16* s, const bf16* pA0h, const bf16* pA0l, const bf16* pA1h, const bf16* pA1l,
    const bf16* pW0h, const bf16* pW0l, const bf16* pW1h, const bf16* pW1l,
    int k0, int t)
{
    const int row = t >> 2;
    const int sub = (t & 3) * 8;       // bf16 elems
    const int so0 = row * KPAD + sub;
    const int so1 = (row + 64) * KPAD + sub;
    const int off = k0 + sub;
    cpa16(s + OFF_AHI + so0, pA0h + off, pA0h != nullptr);
    cpa16(s + OFF_AHI + so1, pA1h + off, pA1h != nullptr);
    cpa16(s + OFF_ALO + so0, pA0l + off, pA0l != nullptr);
    cpa16(s + OFF_ALO + so1, pA1l + off, pA1l != nullptr);
    cpa16(s + OFF_WHI + so0, pW0h + off, true);
    cpa16(s + OFF_WHI + so1, pW1h + off, true);
    cpa16(s + OFF_WLO + so0, pW0l + off, true);
    cpa16(s + OFF_WLO + so1, pW1l + off, true);
}

// compute one 32-wide K slab: warp tile 32x64, 3-way split-bf16 accumulate
__device__ __forceinline__ void hmma_slab(const bf16* s, int wm, int wn, int lane,
                                          float acc[2][8][4])
{
#pragma unroll
    for (int ks = 0; ks < 2; ks++) {
        const int arow = wm * 32 + (lane & 15);
        const int acol = ks * 16 + (lane >> 4) * 8;
        unsigned ahi[2][4], alo[2][4];
#pragma unroll
        for (int mt = 0; mt < 2; mt++) {
            ldsm4(smem_u32(s + OFF_AHI + (arow + mt * 16) * KPAD + acol),
                  ahi[mt][0], ahi[mt][1], ahi[mt][2], ahi[mt][3]);
            ldsm4(smem_u32(s + OFF_ALO + (arow + mt * 16) * KPAD + acol),
                  alo[mt][0], alo[mt][1], alo[mt][2], alo[mt][3]);
        }
        const int brow = wn * 64 + (lane & 7) + ((lane >> 4) << 3);
        const int bcol = ks * 16 + ((lane >> 3) & 1) * 8;
        unsigned bhi[8][2], blo[8][2];
#pragma unroll
        for (int np = 0; np < 4; np++) {
            unsigned r0, r1, r2, r3;
            ldsm4(smem_u32(s + OFF_WHI + (brow + np * 16) * KPAD + bcol), r0, r1, r2, r3);
            bhi[2 * np][0] = r0; bhi[2 * np][1] = r1;
            bhi[2 * np + 1][0] = r2; bhi[2 * np + 1][1] = r3;
            ldsm4(smem_u32(s + OFF_WLO + (brow + np * 16) * KPAD + bcol), r0, r1, r2, r3);
            blo[2 * np][0] = r0; blo[2 * np][1] = r1;
            blo[2 * np + 1][0] = r2; blo[2 * np + 1][1] = r3;
        }
#pragma unroll
        for (int mt = 0; mt < 2; mt++)
#pragma unroll
            for (int nf = 0; nf < 8; nf++) {
                mma16816(acc[mt][nf], ahi[mt], bhi[nf]);
                mma16816(acc[mt][nf], ahi[mt], blo[nf]);
                mma16816(acc[mt][nf], alo[mt], bhi[nf]);
            }
    }
}

// full mainloop: fills acc for this block's 128x128 tile (cp.async pipelined)
__device__ __forceinline__ void hmma_mainloop(
    const bf16* pA0h, const bf16* pA0l, const bf16* pA1h, const bf16* pA1l,
    const bf16* pW0h, const bf16* pW0l, const bf16* pW1h, const bf16* pW1l,
    float acc[2][8][4])
{
    extern __shared__ bf16 sbuf[];
    const int t = threadIdx.x;
    const int wid = t >> 5, lane = t & 31;
    const int wm = wid & 3, wn = wid >> 2;

#pragma unroll
    for (int i = 0; i < 2; i++)
#pragma unroll
        for (int j = 0; j < 8; j++)
#pragma unroll
            for (int v = 0; v < 4; v++) acc[i][j][v] = 0.f;

    load_slab_async(sbuf, pA0h, pA0l, pA1h, pA1l, pW0h, pW0l, pW1h, pW1l, 0, t);
    CP_COMMIT();
    CP_WAIT0();
    __syncthreads();
    for (int sl = 0; sl < 24; sl++) {
        if (sl + 1 < 24) {
            load_slab_async(sbuf + ((sl + 1) & 1) * STAGE_E,
                            pA0h, pA0l, pA1h, pA1l, pW0h, pW0l, pW1h, pW1l,
                            (sl + 1) * 32, t);
            CP_COMMIT();
        }
        hmma_slab(sbuf + (sl & 1) * STAGE_E, wm, wn, lane, acc);
        if (sl + 1 < 24) CP_WAIT0();
        __syncthreads();
    }
}

// ---------------------------------------------------------------------------
// Merged GEMM 1+2: blocks [0,594) do Q projection, blocks [594,750) do the
// gathered K/V projection. Single launch fills the tail wave.
// ---------------------------------------------------------------------------
__global__ __launch_bounds__(256) void gemm_qkv_hmma()
{
    const int bid = blockIdx.x;
    const int t = threadIdx.x;
    const int wid = t >> 5, lane = t & 31;
    const int wm = wid & 3, wn = wid >> 2;
    const int quad = lane >> 2, qp = lane & 3;

    if (bid < 594) {
        // ---- Q projection: 12608 x 768 ----
        const int row0 = (bid / 6) * 128, col0 = (bid % 6) * 128;
        const int rA0 = row0 + (t >> 2), rA1 = rA0 + 64;
        const int cW0 = col0 + (t >> 2), cW1 = cW0 + 64;
        const bf16* pA0h = (rA0 < ROWSn) ? g_xhi + (size_t)rA0 * CC : nullptr;
        const bf16* pA0l = (rA0 < ROWSn) ? g_xlo + (size_t)rA0 * CC : nullptr;
        const bf16* pA1h = (rA1 < ROWSn) ? g_xhi + (size_t)rA1 * CC : nullptr;
        const bf16* pA1l = (rA1 < ROWSn) ? g_xlo + (size_t)rA1 * CC : nullptr;

        float acc[2][8][4];
        hmma_mainloop(pA0h, pA0l, pA1h, pA1l,
                      g_wqhi + (size_t)cW0 * CC, g_wqlo + (size_t)cW0 * CC,
                      g_wqhi + (size_t)cW1 * CC, g_wqlo + (size_t)cW1 * CC, acc);

#pragma unroll
        for (int mt = 0; mt < 2; mt++)
#pragma unroll
            for (int nf = 0; nf < 8; nf++) {
                int r = row0 + wm * 32 + mt * 16 + quad;
                int c = col0 + wn * 64 + nf * 8 + qp * 2;
                __nv_bfloat162 h, l;
                if (r < ROWSn) {
                    split2f(acc[mt][nf][0], acc[mt][nf][1], h, l);
                    *(__nv_bfloat162*)&g_qhi[(size_t)r * CC + c] = h;
                    *(__nv_bfloat162*)&g_qlo[(size_t)r * CC + c] = l;
                }
                if (r + 8 < ROWSn) {
                    split2f(acc[mt][nf][2], acc[mt][nf][3], h, l);
                    *(__nv_bfloat162*)&g_qhi[(size_t)(r + 8) * CC + c] = h;
                    *(__nv_bfloat162*)&g_qlo[(size_t)(r + 8) * CC + c] = l;
                }
            }
    } else {
        // ---- gathered K/V projection: 1632 x 1536 ----
        const int idx = bid - 594;
        const int row0 = (idx / 12) * 128, col0 = (idx % 12) * 128;

        const bf16* pA[2][2] = {{nullptr, nullptr}, {nullptr, nullptr}};
#pragma unroll
        for (int i = 0; i < 2; i++) {
            int gr = row0 + (t >> 2) + i * 64;
            if (gr < GRn) {
                int b = gr / MMn, m = gr - b * MMn;
                size_t src = (size_t)(b * NNt + token_of(m)) * CC;
                pA[i][0] = g_xhi + src; pA[i][1] = g_xlo + src;
            }
        }
        const int cW0 = col0 + (t >> 2), cW1 = cW0 + 64;
        const bf16* wbase_h = g_wqhi + (size_t)768 * CC;
        const bf16* wbase_l = g_wqlo + (size_t)768 * CC;

        float acc[2][8][4];
        hmma_mainloop(pA[0][0], pA[0][1], pA[1][0], pA[1][1],
                      wbase_h + (size_t)cW0 * CC, wbase_l + (size_t)cW0 * CC,
                      wbase_h + (size_t)cW1 * CC, wbase_l + (size_t)cW1 * CC, acc);

#pragma unroll
        for (int mt = 0; mt < 2; mt++)
#pragma unroll
            for (int nf = 0; nf < 8; nf++) {
#pragma unroll
                for (int up = 0; up < 2; up++) {
                    int gr = row0 + wm * 32 + mt * 16 + quad + up * 8;
                    if (gr >= GRn) continue;
                    int b = gr / MMn, m = gr - b * MMn;
                    int c = col0 + wn * 64 + nf * 8 + qp * 2;
                    float vx = acc[mt][nf][2 * up], vy = acc[mt][nf][2 * up + 1];
                    if (c < 768) {
                        int h = c >> 6, d = c & 63;
                        int bh = b * HHn + h;
                        __nv_bfloat162 hh, ll;
                        split2f(vx, vy, hh, ll);
                        size_t g = ((size_t)bh * MMn + m) * HDn + d;
                        *(__nv_bfloat162*)&g_khi[g] = hh;
                        *(__nv_bfloat162*)&g_klo[g] = ll;
                    } else {
                        int c2 = c - 768;
                        int h = c2 >> 6, d = c2 & 63;
                        int bh = b * HHn + h;
                        bf16 h0 = __float2bfloat16(vx);
                        bf16 h1 = __float2bfloat16(vy);
                        bf16 l0 = __float2bfloat16(vx - __bfloat162float(h0));
                        bf16 l1 = __float2bfloat16(vy - __bfloat162float(h1));
                        size_t g0 = ((size_t)bh * HDn + d) * VPP + m;
                        size_t g1 = ((size_t)bh * HDn + d + 1) * VPP + m;
                        g_vthi[g0] = h0; g_vtlo[g0] = l0;
                        g_vthi[g1] = h1; g_vtlo[g1] = l1;
                    }
                }
            }
    }
}

// ---------------------------------------------------------------------------
// Attention (tensor) - R10 design: one block = (bh, 128-query tile), 256 thr.
// Phase A: S = Q K^T (split HMMA, warps 8m x 1n, S in regs 26 frags)
// Phase B: mask, exp, quad row-sum, normalize, split-P -> smem (aliased)
// Phase C: O = P V^T (split HMMA, warps 4m x 2n), epilogue writes g_ohi/olo
// ---------------------------------------------------------------------------
__global__ __launch_bounds__(256) void attn_hmma()
{
    extern __shared__ bf16 sb[];
    const int bh = blockIdx.x, qt = blockIdx.y;
    const int b = bh / HHn, h = bh % HHn;
    const int n0 = qt * 128;
    const int t = threadIdx.x, wid = t >> 5, lane = t & 31;

    // --- loads ---
    for (int i = t; i < 1024; i += 256) {
        int row = i >> 3, u = (i & 7) * 8;
        int qn = n0 + row; if (qn >= NNt) qn = NNt - 1;
        size_t g = (size_t)(b * NNt + qn) * CC + h * HDn + u;
        *(uint4*)(sb + SQHI + row * QKP + u) = *(const uint4*)(g_qhi + g);
        *(uint4*)(sb + SQLO + row * QKP + u) = *(const uint4*)(g_qlo + g);
    }
    const uint4 z4 = make_uint4(0, 0, 0, 0);
    for (int i = t; i < 1664; i += 256) {
        int row = i >> 3, u = (i & 7) * 8;
        uint4 vh = z4, vl = z4;
        if (row < MMn) {
            size_t g = ((size_t)bh * MMn + row) * HDn + u;
            vh = *(const uint4*)(g_khi + g);
            vl = *(const uint4*)(g_klo + g);
        }
        *(uint4*)(sb + SKHI + row * QKP + u) = vh;
        *(uint4*)(sb + SKLO + row * QKP + u) = vl;
    }
    for (int i = t; i < 1728; i += 256) {
        int row = i / 27, u = (i % 27) * 8;
        size_t g = ((size_t)bh * HDn + row) * VPP + u;
        *(uint4*)(sb + SVHI + row * VPP + u) = *(const uint4*)(g_vthi + g);
        *(uint4*)(sb + SVLO + row * VPP + u) = *(const uint4*)(g_vtlo + g);
    }
    __syncthreads();

    // --- Phase A: S = Q K^T, warp owns 16 rows, all 208 key cols ---
    float sacc[26][4];
#pragma unroll
    for (int i = 0; i < 26; i++)
#pragma unroll
        for (int v = 0; v < 4; v++) sacc[i][v] = 0.f;

    const int m0 = wid * 16;
#pragma unroll
    for (int ks = 0; ks < 4; ks++) {
        unsigned ah[4], al[4];
        const int arow = m0 + (lane & 15);
        const int acol = ks * 16 + (lane >> 4) * 8;
        ldsm4(smem_u32(sb + SQHI + arow * QKP + acol), ah[0], ah[1], ah[2], ah[3]);
        ldsm4(smem_u32(sb + SQLO + arow * QKP + acol), al[0], al[1], al[2], al[3]);
        const int brow_base = (lane & 7) + ((lane >> 4) << 3);
        const int bcol = ks * 16 + ((lane >> 3) & 1) * 8;
#pragma unroll
        for (int np = 0; np < 13; np++) {
            unsigned kh[4], kl[4];
            ldsm4(smem_u32(sb + SKHI + (np * 16 + brow_base) * QKP + bcol),
                  kh[0], kh[1], kh[2], kh[3]);
            ldsm4(smem_u32(sb + SKLO + (np * 16 + brow_base) * QKP + bcol),
                  kl[0], kl[1], kl[2], kl[3]);
            mma16816(sacc[2 * np],     ah, kh);
            mma16816(sacc[2 * np],     ah, kl);
            mma16816(sacc[2 * np],     al, kh);
            mma16816(sacc[2 * np + 1], ah, kh + 2);
            mma16816(sacc[2 * np + 1], ah, kl + 2);
            mma16816(sacc[2 * np + 1], al, kh + 2);
        }
    }
    __syncthreads();   // all Q/K smem reads done before P overwrites the region

    // --- Phase B: mask + softmax + normalize + split-P store ---
    const int ra = m0 + (lane >> 2);
    int qa = n0 + ra, qb = qa + 8;
    int qac = qa < NNt ? qa : NNt - 1;
    int qbc = qb < NNt ? qb : NNt - 1;
    int fa = qac / NO, fb = qbc / NO;
    int csa = (fa < 4) ? (8 + 25 * fa) : (108 + 24 * (fa - 4));
    int cea = csa + ((fa < 4) ? 25 : 24);
    int csb = (fb < 4) ? (8 + 25 * fb) : (108 + 24 * (fb - 4));
    int ceb = csb + ((fb < 4) ? 25 : 24);

    float suma = 0.f, sumb = 0.f;
#pragma unroll
    for (int nf = 0; nf < 26; nf++) {
        int c0 = nf * 8 + (lane & 3) * 2;
        int c1 = c0 + 1;
        float ma0 = (c0 < 8 || (c0 >= csa && c0 < cea)) ? 0.125f : 0.1f;
        float ma1 = (c1 < 8 || (c1 >= csa && c1 < cea)) ? 0.125f : 0.1f;
        float mb0 = (c0 < 8 || (c0 >= csb && c0 < ceb)) ? 0.125f : 0.1f;
        float mb1 = (c1 < 8 || (c1 >= csb && c1 < ceb)) ? 0.125f : 0.1f;
        float pa0 = (c0 < MMn) ? __expf(sacc[nf][0] * ma0) : 0.f;
        float pa1 = (c1 < MMn) ? __expf(sacc[nf][1] * ma1) : 0.f;
        float pb0 = (c0 < MMn) ? __expf(sacc[nf][2] * mb0) : 0.f;
        float pb1 = (c1 < MMn) ? __expf(sacc[nf][3] * mb1) : 0.f;
        sacc[nf][0] = pa0; sacc[nf][1] = pa1;
        sacc[nf][2] = pb0; sacc[nf][3] = pb1;
        suma += pa0 + pa1; sumb += pb0 + pb1;
    }
    suma += __shfl_xor_sync(0xffffffffu, suma, 1);
    suma += __shfl_xor_sync(0xffffffffu, suma, 2);
    sumb += __shfl_xor_sync(0xffffffffu, sumb, 1);
    sumb += __shfl_xor_sync(0xffffffffu, sumb, 2);
    const float inva = 1.f / suma, invb = 1.f / sumb;

#pragma unroll
    for (int nf = 0; nf < 26; nf++) {
        int c0 = nf * 8 + (lane & 3) * 2;
        __nv_bfloat162 hh, ll;
        split2f(sacc[nf][0] * inva, sacc[nf][1] * inva, hh, ll);
        *(__nv_bfloat162*)(sb + SPHI + ra * VPP + c0) = hh;
        *(__nv_bfloat162*)(sb + SPLO + ra * VPP + c0) = ll;
        split2f(sacc[nf][2] * invb, sacc[nf][3] * invb, hh, ll);
        *(__nv_bfloat162*)(sb + SPHI + (ra + 8) * VPP + c0) = hh;
        *(__nv_bfloat162*)(sb + SPLO + (ra + 8) * VPP + c0) = ll;
    }
    __syncthreads();

    // --- Phase C: O = P V^T. warps 4m x 2n, warp tile 32x32, K=208 ---
    const int wm = wid & 3, wn = wid >> 2;
    float oacc[2][4][4];
#pragma unroll
    for (int i = 0; i < 2; i++)
#pragma unroll
        for (int j = 0; j < 4; j++)
#pragma unroll
            for (int v = 0; v < 4; v++) oacc[i][j][v] = 0.f;

#pragma unroll 1
    for (int kk = 0; kk < 13; kk++) {
        unsigned ph[2][4], pl[2][4];
        const int acol = kk * 16 + (lane >> 4) * 8;
#pragma unroll
        for (int mt = 0; mt < 2; mt++) {
            const int arow = wm * 32 + mt * 16 + (lane & 15);
            ldsm4(smem_u32(sb + SPHI + arow * VPP + acol),
                  ph[mt][0], ph[mt][1], ph[mt][2], ph[mt][3]);
            ldsm4(smem_u32(sb + SPLO + arow * VPP + acol),
                  pl[mt][0], pl[mt][1], pl[mt][2], pl[mt][3]);
        }
        unsigned vh[4][2], vl[4][2];
        const int brow_base = wn * 32 + (lane & 7) + ((lane >> 4) << 3);
        const int bcol = kk * 16 + ((lane >> 3) & 1) * 8;
#pragma unroll
        for (int np = 0; np < 2; np++) {
            unsigned r0, r1, r2, r3;
            ldsm4(smem_u32(sb + SVHI + (brow_base + np * 16) * VPP + bcol), r0, r1, r2, r3);
            vh[2 * np][0] = r0; vh[2 * np][1] = r1;
            vh[2 * np + 1][0] = r2; vh[2 * np + 1][1] = r3;
            ldsm4(smem_u32(sb + SVLO + (brow_base + np * 16) * VPP + bcol), r0, r1, r2, r3);
            vl[2 * np][0] = r0; vl[2 * np][1] = r1;
            vl[2 * np + 1][0] = r2; vl[2 * np + 1][1] = r3;
        }
#pragma unroll
        for (int mt = 0; mt < 2; mt++)
#pragma unroll
            for (int nf = 0; nf < 4; nf++) {
                mma16816(oacc[mt][nf], ph[mt], vh[nf]);
                mma16816(oacc[mt][nf], pl[mt], vh[nf]);
                mma16816(oacc[mt][nf], ph[mt], vl[nf]);
            }
    }

    // epilogue: split O directly to g_ohi/g_olo (token-major [row][CC])
    const int quad = lane >> 2, qp = lane & 3;
#pragma unroll
    for (int mt = 0; mt < 2; mt++)
#pragma unroll
        for (int nf = 0; nf < 4; nf++) {
            int r = n0 + wm * 32 + mt * 16 + quad;
            int c = h * HDn + wn * 32 + nf * 8 + qp * 2;
            __nv_bfloat162 hh, ll;
            if (r < NNt) {
                size_t g = (size_t)(b * NNt + r) * CC + c;
                split2f(oacc[mt][nf][0], oacc[mt][nf][1], hh, ll);
                *(__nv_bfloat162*)&g_ohi[g] = hh;
                *(__nv_bfloat162*)&g_olo[g] = ll;
            }
            if (r + 8 < NNt) {
                size_t g = (size_t)(b * NNt + r + 8) * CC + c;
                split2f(oacc[mt][nf][2], oacc[mt][nf][3], hh, ll);
                *(__nv_bfloat162*)&g_ohi[g] = hh;
                *(__nv_bfloat162*)&g_olo[g] = ll;
            }
        }
}

// ---------------------------------------------------------------------------
// GEMM 3: out = O @ proj_w^T + proj_b   (12608 x 768, K=768), grid (99, 6)
// ---------------------------------------------------------------------------
__global__ __launch_bounds__(256) void gemm_proj_hmma(
    const float* __restrict__ bias, float* __restrict__ Cout)
{
    const int t = threadIdx.x;
    const int row0 = blockIdx.x * 128, col0 = blockIdx.y * 128;
    const int wid = t >> 5, lane = t & 31;
    const int wm = wid & 3, wn = wid >> 2;

    const int rA0 = row0 + (t >> 2), rA1 = rA0 + 64;
    const int cW0 = col0 + (t >> 2), cW1 = cW0 + 64;
    const bf16* pA0h = (rA0 < ROWSn) ? g_ohi + (size_t)rA0 * CC : nullptr;
    const bf16* pA0l = (rA0 < ROWSn) ? g_olo + (size_t)rA0 * CC : nullptr;
    const bf16* pA1h = (rA1 < ROWSn) ? g_ohi + (size_t)rA1 * CC : nullptr;
    const bf16* pA1l = (rA1 < ROWSn) ? g_olo + (size_t)rA1 * CC : nullptr;

    float acc[2][8][4];
    hmma_mainloop(pA0h, pA0l, pA1h, pA1l,
                  g_wphi + (size_t)cW0 * CC, g_wplo + (size_t)cW0 * CC,
                  g_wphi + (size_t)cW1 * CC, g_wplo + (size_t)cW1 * CC, acc);

    const int quad = lane >> 2, qp = lane & 3;
#pragma unroll
    for (int nf = 0; nf < 8; nf++) {
        int c = col0 + wn * 64 + nf * 8 + qp * 2;
        float2 bv = *(const float2*)&bias[c];
#pragma unroll
        for (int mt = 0; mt < 2; mt++) {
            int r = row0 + wm * 32 + mt * 16 + quad;
            if (r < ROWSn)
                *(float2*)&Cout[(size_t)r * CC + c] =
                    make_float2(acc[mt][nf][0] + bv.x, acc[mt][nf][1] + bv.y);
            if (r + 8 < ROWSn)
                *(float2*)&Cout[(size_t)(r + 8) * CC + c] =
                    make_float2(acc[mt][nf][2] + bv.x, acc[mt][nf][3] + bv.y);
        }
    }
}

// ---------------------------------------------------------------------------
extern "C" void kernel_launch(void* const* d_in, const int* in_sizes, int n_in,
                              void* d_out, int out_size)
{
    const float* x      = (const float*)d_in[0];
    const float* qkv_w  = (const float*)d_in[1];
    const float* proj_w = (const float*)d_in[2];
    const float* proj_b = (const float*)d_in[3];
    float* out = (float*)d_out;

    cudaFuncSetAttribute(gemm_qkv_hmma,
                         cudaFuncAttributeMaxDynamicSharedMemorySize, SMEM_GEMM);
    cudaFuncSetAttribute(gemm_proj_hmma,
                         cudaFuncAttributeMaxDynamicSharedMemorySize, SMEM_GEMM);
    cudaFuncSetAttribute(attn_hmma,
                         cudaFuncAttributeMaxDynamicSharedMemorySize, SMEM_ATT);

    bf16 *xhi, *xlo, *wqhi, *wqlo, *wphi, *wplo;
    cudaGetSymbolAddress((void**)&xhi, g_xhi);
    cudaGetSymbolAddress((void**)&xlo, g_xlo);
    cudaGetSymbolAddress((void**)&wqhi, g_wqhi);
    cudaGetSymbolAddress((void**)&wqlo, g_wqlo);
    cudaGetSymbolAddress((void**)&wphi, g_wphi);
    cudaGetSymbolAddress((void**)&wplo, g_wplo);

    dim3 blk(256);
    int n4x = ROWSn * CC / 4;
    int n4q = 3 * CC * CC / 4;
    int n4p = CC * CC / 4;
    cvt_hilo<<<(n4x + 255) / 256, blk>>>(x, xhi, xlo, n4x);
    cvt_hilo<<<(n4q + 255) / 256, blk>>>(qkv_w, wqhi, wqlo, n4q);
    cvt_hilo<<<(n4p + 255) / 256, blk>>>(proj_w, wphi, wplo, n4p);
    vt_zero_pad<<<NBH, blk>>>();

    // merged Q + K/V projections (594 + 156 blocks)
    gemm_qkv_hmma<<<750, blk, SMEM_GEMM>>>();
    // attention: 96 bh x 13 query tiles of 128, 256 threads (R10 config)
    attn_hmma<<<dim3(NBH, 13), blk, SMEM_ATT>>>();
    // output projection + bias
    gemm_proj_hmma<<<dim3(99, 6), blk, SMEM_GEMM>>>(proj_b, out);
}